// round 9
// baseline (speedup 1.0000x reference)
#include <cuda_runtime.h>
#include <cstdint>

#define LN_EPS 1e-5f
#define D_EPS  1e-6f
#define BATCH  16
#define SEQL   2048
#define NCHUNK 32           // 32 chunks x 64 steps = 2048 (2047 real + 1 pad)

// Scratch
__device__ float g_tab[64 * 64];
__device__ float g_G[64 * 64];                     // Gram
__device__ float g_TW[64 * 64];                    // Tab @ Wr
__device__ float g_rpos[64];                       // 1/(||tab||^2 + eps)
__device__ float g_dpos[64];                       // (||tab||^2 + eps)
__device__ float g_Ainv[BATCH * NCHUNK * 64 * 64]; // per-chunk (I+L)^-1

// ---------------------------------------------------------------------------
__device__ __forceinline__ void cp_async16(uint32_t saddr, const void* gaddr) {
    asm volatile("cp.async.cg.shared.global [%0], [%1], 16;"
                 :: "r"(saddr), "l"(gaddr));
}
__device__ __forceinline__ void cp_commit() {
    asm volatile("cp.async.commit_group;");
}
__device__ __forceinline__ void cp_wait1() {
    asm volatile("cp.async.wait_group 1;");
}

// ---------------------------------------------------------------------------
// K1: per-token table: tab[a] = LN(e_a + MLP(e_a)); rpos/dpos.
// ---------------------------------------------------------------------------
__global__ __launch_bounds__(128) void table_kernel(
    const float* __restrict__ embed, const float* __restrict__ W1,
    const float* __restrict__ b1, const float* __restrict__ W2,
    const float* __restrict__ b2, const float* __restrict__ gamma,
    const float* __restrict__ beta)
{
    __shared__ float hs[64];
    __shared__ float t1s[128];
    __shared__ float xh[2][64];
    __shared__ float red[2][2];

    const int a = blockIdx.x, tid = threadIdx.x;
    if (tid < 64) hs[tid] = embed[a * 64 + tid];
    __syncthreads();

    float acc = b1[tid];
    #pragma unroll
    for (int i = 0; i < 64; i++) acc = fmaf(hs[i], W1[i * 128 + tid], acc);
    t1s[tid] = fmaxf(acc, 0.f);
    __syncthreads();

    {
        int j = tid & 63, half = tid >> 6;
        float a2 = 0.f;
        #pragma unroll
        for (int ii = 0; ii < 64; ii++) {
            int i = half * 64 + ii;
            a2 = fmaf(t1s[i], W2[i * 64 + j], a2);
        }
        xh[half][j] = a2;
    }
    __syncthreads();

    float x = 0.f, y = 0.f;
    if (tid < 64) {
        x = hs[tid] + xh[0][tid] + xh[1][tid] + b2[tid];
        float s = x, q = x * x;
        #pragma unroll
        for (int o = 16; o > 0; o >>= 1) {
            s += __shfl_xor_sync(0xffffffffu, s, o);
            q += __shfl_xor_sync(0xffffffffu, q, o);
        }
        if ((tid & 31) == 0) { red[tid >> 5][0] = s; red[tid >> 5][1] = q; }
    }
    __syncthreads();
    if (tid < 64) {
        float S = red[0][0] + red[1][0];
        float Q = red[0][1] + red[1][1];
        float mu = S * (1.0f / 64.0f);
        float var = Q * (1.0f / 64.0f) - mu * mu;
        y = (x - mu) * rsqrtf(var + LN_EPS) * gamma[tid] + beta[tid];
        g_tab[a * 64 + tid] = y;
        float z = y * y;
        #pragma unroll
        for (int o = 16; o > 0; o >>= 1) z += __shfl_xor_sync(0xffffffffu, z, o);
        if ((tid & 31) == 0) red[tid >> 5][0] = z;
    }
    __syncthreads();
    if (tid == 0) {
        float d = red[0][0] + red[1][0] + D_EPS;
        g_dpos[a] = d;
        g_rpos[a] = 1.0f / d;
    }
}

// ---------------------------------------------------------------------------
// K2: G = Tab Tab^T and TW = Tab @ Wr.
// ---------------------------------------------------------------------------
__global__ __launch_bounds__(64) void gram_kernel(const float* __restrict__ Wr)
{
    __shared__ float T[64][65];
    const int a = blockIdx.x, t = threadIdx.x;
    for (int r = 0; r < 64; r++) T[r][t] = g_tab[r * 64 + t];
    __syncthreads();
    float g = 0.f, tw = 0.f;
    #pragma unroll
    for (int h = 0; h < 64; h++) {
        float av = T[a][h];
        g  = fmaf(av, T[t][h], g);
        tw = fmaf(av, Wr[h * 64 + t], tw);
    }
    g_G[a * 64 + t]  = g;
    g_TW[a * 64 + t] = tw;
}

// ---------------------------------------------------------------------------
// K3: per-chunk prep: Ainv = (I+L)^{-1}, L[t][u] = r_u * G[v_t][v_u] (u<t).
// ---------------------------------------------------------------------------
__global__ __launch_bounds__(64) void prep_kernel(const int* __restrict__ seq)
{
    __shared__ int   vtok[64];
    __shared__ float rr[64];
    __shared__ float Lsh[64][65];

    const int blk = blockIdx.x;
    const int b = blk >> 5, c = blk & 31;
    const int t = threadIdx.x;
    const int* sq = seq + b * SEQL;

    {
        int i = c * 64 + t;                     // reversed global step index
        int v = (i < 2047) ? sq[2046 - i] : 0;  // step 2047 is pad
        vtok[t] = v;
        rr[t]   = (i < 2047) ? g_rpos[v] : 0.f;
    }
    __syncthreads();

    // L row t (strictly lower)
    {
        const float* gr = g_G + vtok[t] * 64;
        for (int u = 0; u < t; u++)
            Lsh[t][u] = rr[u] * gr[vtok[u]];
    }
    __syncthreads();

    // forward substitution: thread t owns column t of X = (I+L)^{-1}
    float X[64];
    #pragma unroll
    for (int i2 = 0; i2 < 64; i2++) X[i2] = (i2 == t) ? 1.f : 0.f;
    #pragma unroll
    for (int u = 0; u < 63; u++) {
        float xu = X[u];
        #pragma unroll
        for (int tt = u + 1; tt < 64; tt++)
            X[tt] = fmaf(-Lsh[tt][u], xu, X[tt]);
    }
    __syncthreads();

    // transpose via smem, then coalesced row store (row-major Ainv[j][l])
    #pragma unroll
    for (int i2 = 0; i2 < 64; i2++) Lsh[i2][t] = X[i2];
    __syncthreads();
    {
        float4* dst = (float4*)(g_Ainv + (size_t)blk * 4096 + t * 64);
        const float* src = &Lsh[t][0];
        #pragma unroll
        for (int j4 = 0; j4 < 16; j4++)
            dst[j4] = make_float4(src[4*j4], src[4*j4+1], src[4*j4+2], src[4*j4+3]);
    }
}

// ---------------------------------------------------------------------------
// K4: chain. 1 block/batch, 256 threads = 64 rows x 4 lanes.
// Ainv streamed by cp.async (distance 2, 3 smem buffers, stride-68 rows).
// Per chunk (4 barriers):
//   A (t<64): p[l] = w[v_l]                 (only gather, 64 LDS)
//   B: t_j = r_j*(Ainv p)_j                 (dense, conflict-free)
//   C (t<64): z[a] = sum_{v_l=a} t_l        (broadcast reads, betareg += z)
//   D: w -= G z                             (dense GEMV, stride-68 Gram)
// Post: beta = betareg*d -> head -> out.
// ---------------------------------------------------------------------------
// smem float offsets  (Gram stride 68 for float4 alignment!)
#define GSTRIDE  68
#define ASTRIDE  68
#define OFF_GP   0            // 64*68  = 4352
#define OFF_AB   4352         // 3*64*68 = 13056 -> ends 17408
#define OFF_RST  17408        // 2048   -> 19456
#define OFF_W    19456        // 64
#define OFF_P    19520        // 64
#define OFF_T    19584        // 64
#define OFF_Z    19648        // 64
#define OFF_VB   19712        // 512 floats = 2048 uchar
#define OFF_HED  20224        // 64
#define SMEM_FLOATS 20288
#define SMEM_BYTES  (SMEM_FLOATS * 4)

__global__ __launch_bounds__(256) void chain_kernel(
    const int* __restrict__ seq,
    const float* __restrict__ br, const float* __restrict__ Wo,
    const float* __restrict__ bo, float* __restrict__ out)
{
    extern __shared__ float sm[];
    float* Gp    = sm + OFF_GP;
    float* Ab    = sm + OFF_AB;
    float* rstep = sm + OFF_RST;
    float* wsh   = sm + OFF_W;
    float* psh   = sm + OFF_P;
    float* tsh   = sm + OFF_T;
    float* zsh   = sm + OFF_Z;
    unsigned char* vb = (unsigned char*)(sm + OFF_VB);
    float* hed   = sm + OFF_HED;

    const int b = blockIdx.x, tid = threadIdx.x;
    const int j = tid >> 2, q = tid & 3;
    const int* sq = seq + b * SEQL;
    const float* Agl = g_Ainv + (size_t)b * NCHUNK * 4096;

    auto issue_chunk = [&](int c) {
        float* buf = Ab + (c % 3) * (64 * ASTRIDE);
        const float* src = Agl + c * 4096;
        #pragma unroll
        for (int k = 0; k < 4; k++) {
            int s = tid + k * 256;
            int row = s >> 4, w16 = s & 15;
            uint32_t sa = (uint32_t)__cvta_generic_to_shared(
                              buf + row * ASTRIDE + w16 * 4);
            cp_async16(sa, src + row * 64 + w16 * 4);
        }
    };

    issue_chunk(0); cp_commit();
    issue_chunk(1); cp_commit();

    // stage Gram (stride 68), token stream, r-per-step, w0
    for (int idx = tid; idx < 4096; idx += 256)
        Gp[(idx >> 6) * GSTRIDE + (idx & 63)] = g_G[idx];
    for (int i = tid; i < SEQL; i += 256) {
        int v = (i < 2047) ? sq[2046 - i] : 0;
        vb[i] = (unsigned char)v;
        rstep[i] = (i < 2047) ? g_rpos[v] : 0.f;
    }
    if (tid < 64) wsh[tid] = g_G[tid * 64 + sq[SEQL - 1]];

    float betareg = 0.f;     // (tid<64 only meaningful)

    for (int c = 0; c < NCHUNK; c++) {
        cp_wait1();
        __syncthreads();          // chunk c staged; prev D done
        if (c + 2 < NCHUNK) issue_chunk(c + 2);
        cp_commit();

        // --- A: gather p ---
        if (tid < 64) psh[tid] = wsh[vb[c * 64 + tid]];
        __syncthreads();

        // --- B: t_j = r_j * (Ainv p)_j ---
        {
            const float* ab = Ab + (c % 3) * (64 * ASTRIDE) + j * ASTRIDE + q * 16;
            const float4* pv = (const float4*)(psh + q * 16);
            float4 a0 = *(const float4*)(ab + 0);
            float4 a1 = *(const float4*)(ab + 4);
            float4 a2 = *(const float4*)(ab + 8);
            float4 a3 = *(const float4*)(ab + 12);
            float4 p0 = pv[0], p1 = pv[1], p2 = pv[2], p3 = pv[3];
            float u0 = fmaf(a0.x, p0.x, a0.y * p0.y);
            u0 = fmaf(a0.z, p0.z, u0); u0 = fmaf(a0.w, p0.w, u0);
            float u1 = fmaf(a1.x, p1.x, a1.y * p1.y);
            u1 = fmaf(a1.z, p1.z, u1); u1 = fmaf(a1.w, p1.w, u1);
            float u2 = fmaf(a2.x, p2.x, a2.y * p2.y);
            u2 = fmaf(a2.z, p2.z, u2); u2 = fmaf(a2.w, p2.w, u2);
            float u3 = fmaf(a3.x, p3.x, a3.y * p3.y);
            u3 = fmaf(a3.z, p3.z, u3); u3 = fmaf(a3.w, p3.w, u3);
            float sv = (u0 + u1) + (u2 + u3);
            sv += __shfl_xor_sync(0xffffffffu, sv, 1);
            sv += __shfl_xor_sync(0xffffffffu, sv, 2);
            if (q == 0) tsh[j] = sv * rstep[c * 64 + j];
        }
        __syncthreads();

        // --- C: z[a] = sum_{v_l==a} t_l  (broadcast reads) ---
        if (tid < 64) {
            const int a = tid;
            float za = 0.f;
            const float4* tv4 = (const float4*)tsh;
            const uchar4* vv4 = (const uchar4*)(vb + c * 64);
            #pragma unroll 4
            for (int l4 = 0; l4 < 16; l4++) {
                float4 tv = tv4[l4];
                uchar4 vv = vv4[l4];
                if (vv.x == a) za += tv.x;
                if (vv.y == a) za += tv.y;
                if (vv.z == a) za += tv.z;
                if (vv.w == a) za += tv.w;
            }
            zsh[a] = za;
            betareg += za;
        }
        __syncthreads();

        // --- D: w[j] -= (G z)_j ---
        {
            const float* gr = Gp + j * GSTRIDE + q * 16;
            const float4* zv = (const float4*)(zsh + q * 16);
            float4 g0 = *(const float4*)(gr + 0);
            float4 g1 = *(const float4*)(gr + 4);
            float4 g2 = *(const float4*)(gr + 8);
            float4 g3 = *(const float4*)(gr + 12);
            float4 z0 = zv[0], z1 = zv[1], z2 = zv[2], z3 = zv[3];
            float u0 = fmaf(g0.x, z0.x, g0.y * z0.y);
            u0 = fmaf(g0.z, z0.z, u0); u0 = fmaf(g0.w, z0.w, u0);
            float u1 = fmaf(g1.x, z1.x, g1.y * z1.y);
            u1 = fmaf(g1.z, z1.z, u1); u1 = fmaf(g1.w, z1.w, u1);
            float u2 = fmaf(g2.x, z2.x, g2.y * z2.y);
            u2 = fmaf(g2.z, z2.z, u2); u2 = fmaf(g2.w, z2.w, u2);
            float u3 = fmaf(g3.x, z3.x, g3.y * z3.y);
            u3 = fmaf(g3.z, z3.z, u3); u3 = fmaf(g3.w, z3.w, u3);
            float du = (u0 + u1) + (u2 + u3);
            du += __shfl_xor_sync(0xffffffffu, du, 1);
            du += __shfl_xor_sync(0xffffffffu, du, 2);
            if (q == 0) wsh[j] -= du;
        }
    }
    __syncthreads();

    // beta[a] = betareg * d_a  (tid<64 holds betareg for token tid)
    float* betash = rstep;   // reuse
    if (tid < 64) betash[tid] = betareg * g_dpos[tid];
    __syncthreads();

    // head: out = (beta @ TW + br) @ Wo + bo
    if (tid < 64) {
        float acc = br[tid];
        #pragma unroll
        for (int a = 0; a < 64; a++)
            acc = fmaf(betash[a], g_TW[a * 64 + tid], acc);
        hed[tid] = acc;
    }
    __syncthreads();
    if (tid < 64) {
        float o = bo[tid];
        #pragma unroll
        for (int k = 0; k < 64; k++)
            o = fmaf(hed[k], Wo[k * 64 + tid], o);
        out[b * 64 + tid] = o;
    }
}

// ---------------------------------------------------------------------------
extern "C" void kernel_launch(void* const* d_in, const int* in_sizes, int n_in,
                              void* d_out, int out_size)
{
    const int*   seq   = (const int*)d_in[0];
    const float* embed = (const float*)d_in[1];
    const float* W1    = (const float*)d_in[2];
    const float* b1    = (const float*)d_in[3];
    const float* W2    = (const float*)d_in[4];
    const float* b2    = (const float*)d_in[5];
    const float* gamma = (const float*)d_in[6];
    const float* beta  = (const float*)d_in[7];
    const float* Wr    = (const float*)d_in[8];
    const float* br    = (const float*)d_in[9];
    const float* Wo    = (const float*)d_in[10];
    const float* bo    = (const float*)d_in[11];
    float* out = (float*)d_out;

    cudaFuncSetAttribute(chain_kernel,
                         cudaFuncAttributeMaxDynamicSharedMemorySize,
                         SMEM_BYTES);

    table_kernel<<<64, 128>>>(embed, W1, b1, W2, b2, gamma, beta);
    gram_kernel<<<64, 64>>>(Wr);
    prep_kernel<<<BATCH * NCHUNK, 64>>>(seq);
    chain_kernel<<<BATCH, 256, SMEM_BYTES>>>(seq, br, Wo, bo, out);
}